// round 16
// baseline (speedup 1.0000x reference)
#include <cuda_runtime.h>
#include <cuda_fp16.h>
#include <cstddef>
#include <cstdint>

#define T_STEPS 512
#define BDIM 64
#define IDIM 128
#define HDIM 1024
#define TBH (BDIM * HDIM)
#define TBI (BDIM * IDIM)

// ---------------- device globals ----------------
__device__ __half g_whf[HDIM * HDIM];     // fp16 hi of W_hh [j][k]
__device__ __half g_wlf[HDIM * HDIM];     // fp16 lo of W_hh
__device__ __half g_wihh[HDIM * IDIM];    // fp16 hi of W_ih
__device__ __half g_wihl[HDIM * IDIM];    // fp16 lo of W_ih
__device__ __half g_xf[T_STEPS * TBI];    // fp16 x
__device__ __half g_hf[2][TBH];           // fp16 h (double buffered)
__device__ unsigned int g_flagQ[4 * 4 * 32];

// ---------------- helpers ----------------
__device__ __forceinline__ float fast_tanh(float x) {
    float e = __expf(2.0f * x);
    return 1.0f - __fdividef(2.0f, e + 1.0f);
}
__device__ __forceinline__ uint32_t smem_u32(const void* p) {
    uint32_t a;
    asm("{ .reg .u64 t; cvta.to.shared.u64 t, %1; cvt.u32.u64 %0, t; }"
        : "=r"(a) : "l"(p));
    return a;
}
__device__ __forceinline__ void ldsm4(uint32_t* r, uint32_t addr) {
    asm volatile("ldmatrix.sync.aligned.m8n8.x4.shared.b16 {%0,%1,%2,%3}, [%4];"
                 : "=r"(r[0]), "=r"(r[1]), "=r"(r[2]), "=r"(r[3]) : "r"(addr));
}
__device__ __forceinline__ void mma16816(float* d, const uint32_t* a, const uint32_t* b) {
    asm volatile(
        "mma.sync.aligned.m16n8k16.row.col.f32.f16.f16.f32 "
        "{%0,%1,%2,%3}, {%4,%5,%6,%7}, {%8,%9}, {%0,%1,%2,%3};"
        : "+f"(d[0]), "+f"(d[1]), "+f"(d[2]), "+f"(d[3])
        : "r"(a[0]), "r"(a[1]), "r"(a[2]), "r"(a[3]), "r"(b[0]), "r"(b[1]));
}
__device__ __forceinline__ void spin_ge(unsigned int* p, unsigned tgt) {
    unsigned v;
    do {
        asm volatile("ld.acquire.gpu.global.u32 %0, [%1];" : "=r"(v) : "l"(p));
    } while (v < tgt);
}
__device__ __forceinline__ void rel_add(unsigned int* p) {
    asm volatile("red.release.gpu.global.add.u32 [%0], %1;"
                 :: "l"(p), "r"(1u) : "memory");
}
#define CP16(dst, src) \
    asm volatile("cp.async.cg.shared.global [%0], [%1], 16;" :: "r"(dst), "l"(src))
#define COMMIT() asm volatile("cp.async.commit_group;" ::: "memory")
#define WAITG(n) asm volatile("cp.async.wait_group %0;" :: "n"(n) : "memory")
#define BARN(id, cnt) \
    asm volatile("bar.sync %0, %1;" :: "r"(id), "r"(cnt) : "memory")

// ---------------------------------------------------------------------------
__global__ void init_kernel(const float* __restrict__ h0) {
    int i = blockIdx.x * blockDim.x + threadIdx.x;
    if (i < 4 * 4 * 32) g_flagQ[i] = 0u;
    if (i < TBH) g_hf[0][i] = __float2half_rn(h0[i]);
}
__global__ void prep_w_kernel(const float* __restrict__ whh,
                              const float* __restrict__ wih) {
    int i = blockIdx.x * blockDim.x + threadIdx.x;
    if (i < HDIM * HDIM) {
        float w = whh[i];
        __half hi = __float2half_rn(w);
        g_whf[i] = hi;
        g_wlf[i] = __float2half_rn(w - __half2float(hi));
    }
    if (i < HDIM * IDIM) {
        float w = wih[i];
        __half hi = __float2half_rn(w);
        g_wihh[i] = hi;
        g_wihl[i] = __float2half_rn(w - __half2float(hi));
    }
}
__global__ void prep_x_kernel(const float* __restrict__ x) {
    int i = blockIdx.x * blockDim.x + threadIdx.x;
    if (i < T_STEPS * TBI) g_xf[i] = __float2half_rn(x[i]);
}

// ---------------------------------------------------------------------------
// fp16 2-pass fused HMMA persistent recurrence, cross-step x prefetch,
// parity-buffered smem (h, x, red). z-MMA runs before the h spins.
// grid (4 bt, 32 jt) = 128 CTAs, 256 threads, 2 k-half groups of 4 warps.
// ---------------------------------------------------------------------------
#define HROW_B 2064
#define XROW_B 272
#define HBUF (16 * HROW_B)                    // 33024
#define XBUF (16 * XROW_B)                    // 4352
#define SM_H 0
#define SM_X (2 * HBUF)                       // 66048
#define SM_RED (SM_X + 2 * XBUF)              // 74752
#define SM_TOT (SM_RED + 8192)                // 82944

__global__ void __launch_bounds__(256, 1)
rec_mma_kernel(const float* __restrict__ bv, float* __restrict__ out) {
    extern __shared__ char smem[];
    const uint32_t sb = smem_u32(smem);

    const int bt = blockIdx.x;          // 0..3
    const int jt = blockIdx.y;          // 0..31
    const int tid = threadIdx.x;
    const int lane = tid & 31;
    const int wid = tid >> 5;
    const int wn = wid & 3;
    const int wk = wid >> 2;
    const int gtid = tid & 127;

    // ---- W_hh fragments (fp16 hi+lo), register-resident ----
    uint32_t whi[32][2], wlo[32][2];
    {
        const int fn = jt * 32 + wn * 8 + (lane >> 2);
        const int fk = wk * 512 + (lane & 3) * 2;
        const __half* wh = g_whf + (size_t)fn * HDIM + fk;
        const __half* wl = g_wlf + (size_t)fn * HDIM + fk;
#pragma unroll
        for (int kc = 0; kc < 32; kc++) {
            whi[kc][0] = *(const uint32_t*)&wh[kc * 16];
            whi[kc][1] = *(const uint32_t*)&wh[kc * 16 + 8];
            wlo[kc][0] = *(const uint32_t*)&wl[kc * 16];
            wlo[kc][1] = *(const uint32_t*)&wl[kc * 16 + 8];
        }
    }
    // ---- W_ih fragments ----
    uint32_t zhi[4][2], zlo[4][2];
    {
        const int fn = jt * 32 + wn * 8 + (lane >> 2);
        const int fk = wk * 64 + (lane & 3) * 2;
        const __half* wh = g_wihh + (size_t)fn * IDIM + fk;
        const __half* wl = g_wihl + (size_t)fn * IDIM + fk;
#pragma unroll
        for (int kc = 0; kc < 4; kc++) {
            zhi[kc][0] = *(const uint32_t*)&wh[kc * 16];
            zhi[kc][1] = *(const uint32_t*)&wh[kc * 16 + 8];
            zlo[kc][0] = *(const uint32_t*)&wl[kc * 16];
            zlo[kc][1] = *(const uint32_t*)&wl[kc * 16 + 8];
        }
    }

    // per-thread fragment/staging offsets (parity added in-loop)
    const uint32_t a_off = (uint32_t)(lane & 15) * HROW_B
                         + ((lane >> 4) << 4) + (uint32_t)wk * 1024u;
    const uint32_t ax_off = (uint32_t)(lane & 15) * XROW_B
                          + ((lane >> 4) << 4) + (uint32_t)wk * 128u;

    // x staging coords (1 CP16/thread)
    const int xrow = gtid >> 3;
    const int xc = gtid & 7;
    const uint32_t xdoff = (uint32_t)xrow * XROW_B + (uint32_t)wk * 128u
                         + (uint32_t)xc * 16;

    // pair-local epilogue coords
    const int ptid = (wk << 5) | lane;
    const int em = ptid >> 2;
    const int ejj = (ptid & 3) << 1;
    const size_t obase = (size_t)(bt * 16 + em) * HDIM + jt * 32 + wn * 8 + ejj;
    const float bz0 = bv[jt * 32 + wn * 8 + ejj];
    const float bz1 = bv[jt * 32 + wn * 8 + ejj + 1];

    unsigned int* fQme = &g_flagQ[(bt * 4 + (jt >> 3)) * 32];
    unsigned int* fQ0 = &g_flagQ[(bt * 4 + 2 * wk) * 32];
    unsigned int* fQ1 = &g_flagQ[(bt * 4 + 2 * wk + 1) * 32];
    const int gbar = 1 + wk;
    const int pbar = 3 + wn;

    // ---- prologue: stage x(0) into parity slot 0 ----
    {
        const size_t xb = (size_t)bt * 16 * IDIM + wk * 64;
        CP16(sb + SM_X + xdoff, g_xf + xb + (size_t)xrow * IDIM + xc * 8);
        COMMIT();   // pending: x(0)
    }

    for (int t = 0; t < T_STEPS; t++) {
        const uint32_t hpar = (uint32_t)(t & 1) * HBUF;
        const uint32_t xpar = (uint32_t)(t & 1) * XBUF;
        float* red = (float*)(smem + SM_RED) + (t & 1) * 1024;

        // ---- x(t) already staged; drain it and run z-MMA (pre-spin work) ----
        float acc[4][4];
#pragma unroll
        for (int b = 0; b < 4; b++)
#pragma unroll
            for (int c = 0; c < 4; c++) acc[b][c] = 0.f;

        WAITG(0);               // drains x(t) (landed long ago for t>0)
        BARN(gbar, 128);
#pragma unroll
        for (int kc = 0; kc < 4; kc++) {
            uint32_t ah[4];
            ldsm4(ah, sb + SM_X + xpar + ax_off + (uint32_t)(kc * 32));
            const int p = kc & 1;
            mma16816(acc[p],     ah, zhi[kc]);
            mma16816(acc[2 + p], ah, zlo[kc]);
        }

        const __half* hsrc = g_hf[t & 1] + (size_t)bt * 16 * HDIM;

        // ---- spin + stage quarter q0 ----
        if (t > 0) spin_ge(fQ0, 64u * (unsigned)t);
#pragma unroll
        for (int it = 0; it < 4; it++) {
            int idx = gtid + (it << 7);
            int row = idx >> 5;
            int c = idx & 31;
            uint32_t doff = SM_H + hpar + (uint32_t)row * HROW_B
                          + (uint32_t)(2 * wk) * 512u + (uint32_t)c * 16;
            CP16(sb + doff, hsrc + (size_t)row * HDIM + (2 * wk) * 256 + c * 8);
        }
        COMMIT();   // pending: q0

        // ---- spin + stage quarter q1 ----
        if (t > 0) spin_ge(fQ1, 64u * (unsigned)t);
#pragma unroll
        for (int it = 0; it < 4; it++) {
            int idx = gtid + (it << 7);
            int row = idx >> 5;
            int c = idx & 31;
            uint32_t doff = SM_H + hpar + (uint32_t)row * HROW_B
                          + (uint32_t)(2 * wk + 1) * 512u + (uint32_t)c * 16;
            CP16(sb + doff, hsrc + (size_t)row * HDIM + (2 * wk + 1) * 256 + c * 8);
        }
        COMMIT();   // pending: q0, q1

        // ---- q0 MMA (q1 in flight) ----
        WAITG(1);
        BARN(gbar, 128);
#pragma unroll
        for (int kc = 0; kc < 16; kc++) {
            uint32_t ah[4];
            ldsm4(ah, sb + SM_H + hpar + a_off + (uint32_t)(kc * 32));
            const int p = kc & 1;
            mma16816(acc[p],     ah, whi[kc]);
            mma16816(acc[2 + p], ah, wlo[kc]);
        }

        // ---- q1 MMA ----
        WAITG(0);
        BARN(gbar, 128);
#pragma unroll
        for (int kc = 16; kc < 32; kc++) {
            uint32_t ah[4];
            ldsm4(ah, sb + SM_H + hpar + a_off + (uint32_t)(kc * 32));
            const int p = kc & 1;
            mma16816(acc[p],     ah, whi[kc]);
            mma16816(acc[2 + p], ah, wlo[kc]);
        }

        // ---- prefetch x(t+1) into other parity slot (off-chain) ----
        if (t + 1 < T_STEPS) {
            const size_t xb = (size_t)(t + 1) * TBI + (size_t)bt * 16 * IDIM + wk * 64;
            CP16(sb + SM_X + ((uint32_t)((t + 1) & 1) * XBUF) + xdoff,
                 g_xf + xb + (size_t)xrow * IDIM + xc * 8);
        }
        COMMIT();   // pending: x(t+1)

        float facc[4];
#pragma unroll
        for (int c = 0; c < 4; c++)
            facc[c] = (acc[0][c] + acc[1][c]) + (acc[2][c] + acc[3][c]);

        // ---- pair-local k-reduce (parity red) ----
        {
            const int dr = lane >> 2;
            const int dc = (lane & 3) * 2;
            float* rw = red + wid * 128;
            rw[dr * 8 + dc] = facc[0];
            rw[dr * 8 + dc + 1] = facc[1];
            rw[(dr + 8) * 8 + dc] = facc[2];
            rw[(dr + 8) * 8 + dc + 1] = facc[3];
        }
        BARN(pbar, 64);

        float2 v0 = *(const float2*)&red[wn * 128 + em * 8 + ejj];
        float2 v1 = *(const float2*)&red[(4 + wn) * 128 + em * 8 + ejj];
        float h0v = fast_tanh(bz0 + v0.x + v1.x);
        float h1v = fast_tanh(bz1 + v0.y + v1.y);

        // ---- h(t+1), release, THEN out ----
        const int nb = (t + 1) & 1;
        __half2 hp;
        hp.x = __float2half_rn(h0v);
        hp.y = __float2half_rn(h1v);
        *(__half2*)&g_hf[nb][obase] = hp;

        __syncwarp();
        if (lane == 0) rel_add(fQme);

        const size_t tb = (size_t)t * TBH;
        *(float2*)&out[tb + obase] = make_float2(h0v, h1v);
    }
}

// ---------------------------------------------------------------------------
__global__ void tail_kernel(float* __restrict__ out) {
    int i = blockIdx.x * blockDim.x + threadIdx.x;
    if (i < TBH) {
        out[(size_t)T_STEPS * TBH + i] = out[(size_t)(T_STEPS - 1) * TBH + i];
    }
}

// ---------------------------------------------------------------------------
extern "C" void kernel_launch(void* const* d_in, const int* in_sizes, int n_in,
                              void* d_out, int out_size) {
    const float *x = nullptr, *h0 = nullptr, *wih = nullptr, *whh = nullptr, *bv = nullptr;
    for (int i = 0; i < n_in; i++) {
        switch (in_sizes[i]) {
            case T_STEPS * BDIM * IDIM: x   = (const float*)d_in[i]; break;
            case BDIM * HDIM:           h0  = (const float*)d_in[i]; break;
            case HDIM * IDIM:           wih = (const float*)d_in[i]; break;
            case HDIM * HDIM:           whh = (const float*)d_in[i]; break;
            case HDIM:                  bv  = (const float*)d_in[i]; break;
            default: break;
        }
    }
    float* out = (float*)d_out;

    cudaFuncSetAttribute(rec_mma_kernel, cudaFuncAttributeMaxDynamicSharedMemorySize, SM_TOT);

    init_kernel<<<256, 256>>>(h0);
    prep_w_kernel<<<4096, 256>>>(whh, wih);
    prep_x_kernel<<<16384, 256>>>(x);
    rec_mma_kernel<<<dim3(4, 32), 256, SM_TOT>>>(bv, out);
    if (out_size >= T_STEPS * TBH + TBH) {
        tail_kernel<<<256, 256>>>(out);
    }
}

// round 17
// speedup vs baseline: 1.0651x; 1.0651x over previous
#include <cuda_runtime.h>
#include <cuda_fp16.h>
#include <cstddef>
#include <cstdint>

#define T_STEPS 512
#define BDIM 64
#define IDIM 128
#define HDIM 1024
#define TBH (BDIM * HDIM)
#define TBI (BDIM * IDIM)

// ---------------- device globals ----------------
__device__ __half g_whf[HDIM * HDIM];     // fp16 W_hh [j][k] (single)
__device__ __half g_wihh[HDIM * IDIM];    // fp16 hi of W_ih
__device__ __half g_wihl[HDIM * IDIM];    // fp16 lo of W_ih
__device__ __half g_xf[T_STEPS * TBI];    // fp16 x
__device__ __half g_hf[2][TBH];           // fp16 h (double buffered)
__device__ unsigned int g_flagQ[4 * 4 * 32];

// ---------------- helpers ----------------
__device__ __forceinline__ float fast_tanh(float x) {
    float e = __expf(2.0f * x);
    return 1.0f - __fdividef(2.0f, e + 1.0f);
}
__device__ __forceinline__ uint32_t smem_u32(const void* p) {
    uint32_t a;
    asm("{ .reg .u64 t; cvta.to.shared.u64 t, %1; cvt.u32.u64 %0, t; }"
        : "=r"(a) : "l"(p));
    return a;
}
__device__ __forceinline__ void ldsm4(uint32_t* r, uint32_t addr) {
    asm volatile("ldmatrix.sync.aligned.m8n8.x4.shared.b16 {%0,%1,%2,%3}, [%4];"
                 : "=r"(r[0]), "=r"(r[1]), "=r"(r[2]), "=r"(r[3]) : "r"(addr));
}
__device__ __forceinline__ void mma16816(float* d, const uint32_t* a, const uint32_t* b) {
    asm volatile(
        "mma.sync.aligned.m16n8k16.row.col.f32.f16.f16.f32 "
        "{%0,%1,%2,%3}, {%4,%5,%6,%7}, {%8,%9}, {%0,%1,%2,%3};"
        : "+f"(d[0]), "+f"(d[1]), "+f"(d[2]), "+f"(d[3])
        : "r"(a[0]), "r"(a[1]), "r"(a[2]), "r"(a[3]), "r"(b[0]), "r"(b[1]));
}
__device__ __forceinline__ void spin_ge(unsigned int* p, unsigned tgt) {
    unsigned v;
    do {
        asm volatile("ld.acquire.gpu.global.u32 %0, [%1];" : "=r"(v) : "l"(p));
    } while (v < tgt);
}
__device__ __forceinline__ void rel_add(unsigned int* p) {
    asm volatile("red.release.gpu.global.add.u32 [%0], %1;"
                 :: "l"(p), "r"(1u) : "memory");
}
#define CP16(dst, src) \
    asm volatile("cp.async.cg.shared.global [%0], [%1], 16;" :: "r"(dst), "l"(src))
#define COMMIT() asm volatile("cp.async.commit_group;" ::: "memory")
#define WAITG(n) asm volatile("cp.async.wait_group %0;" :: "n"(n) : "memory")
#define BARN(id, cnt) \
    asm volatile("bar.sync %0, %1;" :: "r"(id), "r"(cnt) : "memory")

// ---------------------------------------------------------------------------
__global__ void init_kernel(const float* __restrict__ h0) {
    int i = blockIdx.x * blockDim.x + threadIdx.x;
    if (i < 4 * 4 * 32) g_flagQ[i] = 0u;
    if (i < TBH) g_hf[0][i] = __float2half_rn(h0[i]);
}
__global__ void prep_w_kernel(const float* __restrict__ whh,
                              const float* __restrict__ wih) {
    int i = blockIdx.x * blockDim.x + threadIdx.x;
    if (i < HDIM * HDIM) g_whf[i] = __float2half_rn(whh[i]);
    if (i < HDIM * IDIM) {
        float w = wih[i];
        __half hi = __float2half_rn(w);
        g_wihh[i] = hi;
        g_wihl[i] = __float2half_rn(w - __half2float(hi));
    }
}
__global__ void prep_x_kernel(const float* __restrict__ x) {
    int i = blockIdx.x * blockDim.x + threadIdx.x;
    if (i < T_STEPS * TBI) g_xf[i] = __float2half_rn(x[i]);
}

// ---------------------------------------------------------------------------
// fp16 single-pass-W fused HMMA persistent recurrence (R15 structure).
// grid (4 bt, 32 jt) = 128 CTAs, 256 threads, 2 k-half groups of 4 warps.
// ---------------------------------------------------------------------------
#define HROW_B 2064
#define XROW_B 272
#define SM_H 0
#define SM_X (16 * HROW_B)                   // 33024
#define SM_RED (SM_X + 16 * XROW_B)          // 37376
#define SM_TOT (SM_RED + 8192)               // 45568

__global__ void __launch_bounds__(256, 1)
rec_mma_kernel(const float* __restrict__ bv, float* __restrict__ out) {
    extern __shared__ char smem[];
    const uint32_t sb = smem_u32(smem);

    const int bt = blockIdx.x;          // 0..3
    const int jt = blockIdx.y;          // 0..31
    const int tid = threadIdx.x;
    const int lane = tid & 31;
    const int wid = tid >> 5;
    const int wn = wid & 3;
    const int wk = wid >> 2;
    const int gtid = tid & 127;

    // ---- W_hh fragments (single fp16), register-resident ----
    uint32_t whi[32][2];
    {
        const int fn = jt * 32 + wn * 8 + (lane >> 2);
        const int fk = wk * 512 + (lane & 3) * 2;
        const __half* wh = g_whf + (size_t)fn * HDIM + fk;
#pragma unroll
        for (int kc = 0; kc < 32; kc++) {
            whi[kc][0] = *(const uint32_t*)&wh[kc * 16];
            whi[kc][1] = *(const uint32_t*)&wh[kc * 16 + 8];
        }
    }
    // ---- W_ih fragments (hi+lo) ----
    uint32_t zhi[4][2], zlo[4][2];
    {
        const int fn = jt * 32 + wn * 8 + (lane >> 2);
        const int fk = wk * 64 + (lane & 3) * 2;
        const __half* wh = g_wihh + (size_t)fn * IDIM + fk;
        const __half* wl = g_wihl + (size_t)fn * IDIM + fk;
#pragma unroll
        for (int kc = 0; kc < 4; kc++) {
            zhi[kc][0] = *(const uint32_t*)&wh[kc * 16];
            zhi[kc][1] = *(const uint32_t*)&wh[kc * 16 + 8];
            zlo[kc][0] = *(const uint32_t*)&wl[kc * 16];
            zlo[kc][1] = *(const uint32_t*)&wl[kc * 16 + 8];
        }
    }

    const uint32_t a_base = sb + SM_H + (uint32_t)(lane & 15) * HROW_B
                          + ((lane >> 4) << 4) + (uint32_t)wk * 1024u;
    const uint32_t ax_base = sb + SM_X + (uint32_t)(lane & 15) * XROW_B
                           + ((lane >> 4) << 4) + (uint32_t)wk * 128u;

    // pair-local epilogue coords
    const int ptid = (wk << 5) | lane;
    const int em = ptid >> 2;
    const int ejj = (ptid & 3) << 1;
    const size_t obase = (size_t)(bt * 16 + em) * HDIM + jt * 32 + wn * 8 + ejj;
    const float bz0 = bv[jt * 32 + wn * 8 + ejj];
    const float bz1 = bv[jt * 32 + wn * 8 + ejj + 1];

    unsigned int* fQme = &g_flagQ[(bt * 4 + (jt >> 3)) * 32];
    unsigned int* fQ0 = &g_flagQ[(bt * 4 + 2 * wk) * 32];
    unsigned int* fQ1 = &g_flagQ[(bt * 4 + 2 * wk + 1) * 32];
    const int gbar = 1 + wk;
    const int pbar = 3 + wn;

    for (int t = 0; t < T_STEPS; t++) {
        float* red = (float*)(smem + SM_RED) + (t & 1) * 1024;

        // ---- stage x_t slice: 1 CP16/thread ----
        {
            const size_t xb = (size_t)t * TBI + (size_t)bt * 16 * IDIM + wk * 64;
            int row = gtid >> 3;
            int c = gtid & 7;
            uint32_t doff = SM_X + (uint32_t)row * XROW_B + (uint32_t)wk * 128u
                          + (uint32_t)c * 16;
            CP16(sb + doff, g_xf + xb + (size_t)row * IDIM + c * 8);
            COMMIT();   // group 1: x
        }

        const __half* hsrc = g_hf[t & 1] + (size_t)bt * 16 * HDIM;

        // ---- spin + stage quarter q0 ----
        if (t > 0) spin_ge(fQ0, 64u * (unsigned)t);
#pragma unroll
        for (int it = 0; it < 4; it++) {
            int idx = gtid + (it << 7);
            int row = idx >> 5;
            int c = idx & 31;
            uint32_t doff = SM_H + (uint32_t)row * HROW_B
                          + (uint32_t)(2 * wk) * 512u + (uint32_t)c * 16;
            CP16(sb + doff, hsrc + (size_t)row * HDIM + (2 * wk) * 256 + c * 8);
        }
        COMMIT();   // group 2: q0

        // ---- spin + stage quarter q1 ----
        if (t > 0) spin_ge(fQ1, 64u * (unsigned)t);
#pragma unroll
        for (int it = 0; it < 4; it++) {
            int idx = gtid + (it << 7);
            int row = idx >> 5;
            int c = idx & 31;
            uint32_t doff = SM_H + (uint32_t)row * HROW_B
                          + (uint32_t)(2 * wk + 1) * 512u + (uint32_t)c * 16;
            CP16(sb + doff, hsrc + (size_t)row * HDIM + (2 * wk + 1) * 256 + c * 8);
        }
        COMMIT();   // group 3: q1

        // ---- z-MMA + q0 MMA (x, q0 landed; q1 in flight) ----
        float acc[2][4];
#pragma unroll
        for (int b = 0; b < 2; b++)
#pragma unroll
            for (int c = 0; c < 4; c++) acc[b][c] = 0.f;

        WAITG(1);
        BARN(gbar, 128);
#pragma unroll
        for (int kc = 0; kc < 4; kc++) {
            uint32_t ah[4];
            ldsm4(ah, ax_base + (uint32_t)(kc * 32));
            const int p = kc & 1;
            mma16816(acc[p],     ah, zhi[kc]);
            mma16816(acc[p ^ 1], ah, zlo[kc]);
        }
#pragma unroll
        for (int kc = 0; kc < 16; kc++) {
            uint32_t ah[4];
            ldsm4(ah, a_base + (uint32_t)(kc * 32));
            mma16816(acc[kc & 1], ah, whi[kc]);
        }

        // ---- q1 MMA ----
        WAITG(0);
        BARN(gbar, 128);
#pragma unroll
        for (int kc = 16; kc < 32; kc++) {
            uint32_t ah[4];
            ldsm4(ah, a_base + (uint32_t)(kc * 32));
            mma16816(acc[kc & 1], ah, whi[kc]);
        }
        // close smem reuse window before next step's staging
        BARN(gbar, 128);

        float facc[4];
#pragma unroll
        for (int c = 0; c < 4; c++)
            facc[c] = acc[0][c] + acc[1][c];

        // ---- pair-local k-reduce (parity red) ----
        {
            const int dr = lane >> 2;
            const int dc = (lane & 3) * 2;
            float* rw = red + wid * 128;
            rw[dr * 8 + dc] = facc[0];
            rw[dr * 8 + dc + 1] = facc[1];
            rw[(dr + 8) * 8 + dc] = facc[2];
            rw[(dr + 8) * 8 + dc + 1] = facc[3];
        }
        BARN(pbar, 64);

        float2 v0 = *(const float2*)&red[wn * 128 + em * 8 + ejj];
        float2 v1 = *(const float2*)&red[(4 + wn) * 128 + em * 8 + ejj];
        float h0v = fast_tanh(bz0 + v0.x + v1.x);
        float h1v = fast_tanh(bz1 + v0.y + v1.y);

        // ---- h(t+1), release, THEN out ----
        const int nb = (t + 1) & 1;
        __half2 hp;
        hp.x = __float2half_rn(h0v);
        hp.y = __float2half_rn(h1v);
        *(__half2*)&g_hf[nb][obase] = hp;

        __syncwarp();
        if (lane == 0) rel_add(fQme);

        const size_t tb = (size_t)t * TBH;
        *(float2*)&out[tb + obase] = make_float2(h0v, h1v);
    }
}

// ---------------------------------------------------------------------------
__global__ void tail_kernel(float* __restrict__ out) {
    int i = blockIdx.x * blockDim.x + threadIdx.x;
    if (i < TBH) {
        out[(size_t)T_STEPS * TBH + i] = out[(size_t)(T_STEPS - 1) * TBH + i];
    }
}

// ---------------------------------------------------------------------------
extern "C" void kernel_launch(void* const* d_in, const int* in_sizes, int n_in,
                              void* d_out, int out_size) {
    const float *x = nullptr, *h0 = nullptr, *wih = nullptr, *whh = nullptr, *bv = nullptr;
    for (int i = 0; i < n_in; i++) {
        switch (in_sizes[i]) {
            case T_STEPS * BDIM * IDIM: x   = (const float*)d_in[i]; break;
            case BDIM * HDIM:           h0  = (const float*)d_in[i]; break;
            case HDIM * IDIM:           wih = (const float*)d_in[i]; break;
            case HDIM * HDIM:           whh = (const float*)d_in[i]; break;
            case HDIM:                  bv  = (const float*)d_in[i]; break;
            default: break;
        }
    }
    float* out = (float*)d_out;

    cudaFuncSetAttribute(rec_mma_kernel, cudaFuncAttributeMaxDynamicSharedMemorySize, SM_TOT);

    init_kernel<<<256, 256>>>(h0);
    prep_w_kernel<<<4096, 256>>>(whh, wih);
    prep_x_kernel<<<16384, 256>>>(x);
    rec_mma_kernel<<<dim3(4, 32), 256, SM_TOT>>>(bv, out);
    if (out_size >= T_STEPS * TBH + TBH) {
        tail_kernel<<<256, 256>>>(out);
    }
}